// round 1
// baseline (speedup 1.0000x reference)
#include <cuda_runtime.h>
#include <cuda_bf16.h>

// ---------------------------------------------------------------------------
// Problem constants (fixed by the reference generator)
// ---------------------------------------------------------------------------
#define BB   128          // batch (graphs)
#define NP   500          // p-net nodes per graph
#define NV   20           // v-net nodes per graph
#define DD   256          // embedding dim
#define FP   8            // p feature dim
#define FV   6            // v feature dim
#define NPT  (BB*NP)      // 64000 total p nodes
#define NVT  (BB*NV)      // 2560 total v nodes
#define EP   (NPT*8)      // 512000 p edges
#define EV   (NVT*8)      // 20480 v edges
#define CAP  64           // adjacency-list capacity per node (deg ~ Binomial(4000,1/500), mean 8)

// ---------------------------------------------------------------------------
// Scratch (static __device__ arrays — no allocation allowed)
// ---------------------------------------------------------------------------
__device__ float g_p_init[NPT * DD];
__device__ float g_p_bufA[NPT * DD];
__device__ float g_p_bufB[NPT * DD];
__device__ int   g_p_cnt[NPT];
__device__ float g_p_dinv[NPT];
__device__ int   g_p_list[NPT * CAP];
__device__ float g_p_graph[BB * DD];

__device__ float g_v_init[NVT * DD];
__device__ float g_v_bufA[NVT * DD];
__device__ float g_v_bufB[NVT * DD];
__device__ int   g_v_cnt[NVT];
__device__ float g_v_dinv[NVT];
__device__ int   g_v_list[NVT * CAP];
__device__ float g_v_add[BB * DD];

// ---------------------------------------------------------------------------
// float4 helpers
// ---------------------------------------------------------------------------
__device__ __forceinline__ float4 f4_fma(float4 a, float s, float4 acc) {
    acc.x = fmaf(a.x, s, acc.x); acc.y = fmaf(a.y, s, acc.y);
    acc.z = fmaf(a.z, s, acc.z); acc.w = fmaf(a.w, s, acc.w);
    return acc;
}
__device__ __forceinline__ float4 f4_add(float4 a, float4 b) {
    return make_float4(a.x+b.x, a.y+b.y, a.z+b.z, a.w+b.w);
}
__device__ __forceinline__ float4 f4_scale(float4 a, float s) {
    return make_float4(a.x*s, a.y*s, a.z*s, a.w*s);
}
__device__ __forceinline__ float4 f4_relu(float4 a) {
    return make_float4(fmaxf(a.x,0.f), fmaxf(a.y,0.f), fmaxf(a.z,0.f), fmaxf(a.w,0.f));
}

// ---------------------------------------------------------------------------
// 0) zero the counters / accumulators used this call
// ---------------------------------------------------------------------------
__global__ void zero_kernel() {
    int i = blockIdx.x * blockDim.x + threadIdx.x;     // grid covers 64000
    if (i < NPT)        g_p_cnt[i] = 0;
    if (i < NVT)        g_v_cnt[i] = 0;
    if (i < BB * DD)    g_p_graph[i] = 0.0f;
}

// ---------------------------------------------------------------------------
// 1) build per-dst adjacency list (fixed capacity)
// ---------------------------------------------------------------------------
__global__ void build_adj(const int* __restrict__ src, const int* __restrict__ dst,
                          int* __restrict__ cnt, int* __restrict__ list, int E) {
    int e = blockIdx.x * blockDim.x + threadIdx.x;
    if (e >= E) return;
    int d = dst[e];
    int slot = atomicAdd(&cnt[d], 1);
    if (slot < CAP) list[d * CAP + slot] = src[e];
}

// ---------------------------------------------------------------------------
// 2) dinv = rsqrt(deg), deg = cnt + 1 (self loop)
// ---------------------------------------------------------------------------
__global__ void compute_dinv(const int* __restrict__ cnt, float* __restrict__ dinv, int N) {
    int i = blockIdx.x * blockDim.x + threadIdx.x;
    if (i < N) dinv[i] = rsqrtf((float)(cnt[i] + 1));
}

// ---------------------------------------------------------------------------
// 3) init embedding: out = x @ W + b      (x: [N,F], W: [F,256])
// ---------------------------------------------------------------------------
template<int F>
__global__ void init_gemm(const float* __restrict__ x, const float* __restrict__ W,
                          const float* __restrict__ b, float* __restrict__ out) {
    __shared__ float Ws[F * DD];
    __shared__ float xs[32 * F];
    __shared__ float bs[DD];
    int t = threadIdx.x;                   // 256 threads, one output column each
    for (int i = t; i < F * DD; i += 256) Ws[i] = W[i];
    bs[t] = b[t];
    int row0 = blockIdx.x * 32;
    for (int i = t; i < 32 * F; i += 256) xs[i] = x[row0 * F + i];
    __syncthreads();
    float bias = bs[t];
    #pragma unroll 4
    for (int r = 0; r < 32; r++) {
        float s = bias;
        #pragma unroll
        for (int k = 0; k < F; k++) s = fmaf(xs[r * F + k], Ws[k * DD + t], s);
        out[(row0 + r) * DD + t] = s;
    }
}

// ---------------------------------------------------------------------------
// 4) SGEMM: C[M,256] = A[M,256] @ W[256,256]   (M divisible by 128)
//    128x128 block tile, BK=8, 8x8 per thread, 256 threads
// ---------------------------------------------------------------------------
__global__ __launch_bounds__(256, 2)
void sgemm_256(const float* __restrict__ A, const float* __restrict__ W,
               float* __restrict__ C) {
    __shared__ float As[8][128];
    __shared__ float Bs[8][128];
    int tid = threadIdx.x;
    int tx = tid & 15;          // 0..15
    int ty = tid >> 4;          // 0..15
    int rowBase = blockIdx.x * 128;
    int colBase = blockIdx.y * 128;

    int aRow  = tid >> 1;       // 0..127
    int aCol4 = (tid & 1) * 4;  // 0 or 4
    int bRow  = tid >> 5;       // 0..7
    int bCol4 = (tid & 31) * 4; // 0..124

    float acc[8][8];
    #pragma unroll
    for (int i = 0; i < 8; i++)
        #pragma unroll
        for (int j = 0; j < 8; j++) acc[i][j] = 0.0f;

    for (int k0 = 0; k0 < 256; k0 += 8) {
        float4 a4 = *(const float4*)&A[(rowBase + aRow) * 256 + k0 + aCol4];
        As[aCol4 + 0][aRow] = a4.x;
        As[aCol4 + 1][aRow] = a4.y;
        As[aCol4 + 2][aRow] = a4.z;
        As[aCol4 + 3][aRow] = a4.w;
        *(float4*)&Bs[bRow][bCol4] =
            *(const float4*)&W[(k0 + bRow) * 256 + colBase + bCol4];
        __syncthreads();
        #pragma unroll
        for (int k = 0; k < 8; k++) {
            float ra[8], rb[8];
            *(float4*)&ra[0] = *(const float4*)&As[k][ty * 8 + 0];
            *(float4*)&ra[4] = *(const float4*)&As[k][ty * 8 + 4];
            *(float4*)&rb[0] = *(const float4*)&Bs[k][tx * 8 + 0];
            *(float4*)&rb[4] = *(const float4*)&Bs[k][tx * 8 + 4];
            #pragma unroll
            for (int i = 0; i < 8; i++)
                #pragma unroll
                for (int j = 0; j < 8; j++)
                    acc[i][j] = fmaf(ra[i], rb[j], acc[i][j]);
        }
        __syncthreads();
    }
    #pragma unroll
    for (int i = 0; i < 8; i++) {
        int r = rowBase + ty * 8 + i;
        #pragma unroll
        for (int j = 0; j < 8; j += 4) {
            float4 v = make_float4(acc[i][j], acc[i][j+1], acc[i][j+2], acc[i][j+3]);
            *(float4*)&C[r * 256 + colBase + tx * 8 + j] = v;
        }
    }
}

// ---------------------------------------------------------------------------
// 5) GCN aggregation (gather form), one warp per node:
//    out[d] = sum_{e:dst=d} h[src]*dinv[src]*dinv[d] + h[d]/deg[d] + bias  (+relu)
// ---------------------------------------------------------------------------
__global__ void agg_kernel(const float* __restrict__ h, const int* __restrict__ cnt,
                           const float* __restrict__ dinv, const int* __restrict__ list,
                           const float* __restrict__ bias, float* __restrict__ out,
                           int N, int doRelu) {
    int w = (blockIdx.x * blockDim.x + threadIdx.x) >> 5;
    int lane = threadIdx.x & 31;
    if (w >= N) return;
    int rawc = cnt[w];
    int c = rawc < CAP ? rawc : CAP;
    float dd = dinv[w];
    float selfw = 1.0f / (float)(rawc + 1);

    const float4* h4 = (const float4*)h;
    float4 acc0 = f4_scale(h4[(size_t)w * 64 + lane], selfw);
    float4 acc1 = f4_scale(h4[(size_t)w * 64 + 32 + lane], selfw);

    const int* mylist = &list[w * CAP];
    for (int j = 0; j < c; j++) {
        int s = mylist[j];                 // uniform across warp (broadcast)
        float cf = dinv[s] * dd;
        acc0 = f4_fma(h4[(size_t)s * 64 + lane], cf, acc0);
        acc1 = f4_fma(h4[(size_t)s * 64 + 32 + lane], cf, acc1);
    }
    const float4* b4 = (const float4*)bias;
    acc0 = f4_add(acc0, b4[lane]);
    acc1 = f4_add(acc1, b4[32 + lane]);
    if (doRelu) { acc0 = f4_relu(acc0); acc1 = f4_relu(acc1); }
    float4* o4 = (float4*)out;
    o4[(size_t)w * 64 + lane]      = acc0;
    o4[(size_t)w * 64 + 32 + lane] = acc1;
}

// ---------------------------------------------------------------------------
// 6) v-net finalize: v_add[b] = 2*mean_i(node[b,i]) + node[b,cid] + init[b,cid]
// ---------------------------------------------------------------------------
__global__ void v_final_kernel(const float* __restrict__ node, const float* __restrict__ init,
                               const int* __restrict__ curr, float* __restrict__ vadd) {
    int b = blockIdx.x;
    int d = threadIdx.x;
    float s = 0.0f;
    #pragma unroll
    for (int i = 0; i < NV; i++) s += node[(b * NV + i) * DD + d];
    float g = s * (1.0f / (float)NV);
    int cid = curr[b];
    vadd[b * DD + d] = 2.0f * g + node[(b * NV + cid) * DD + d]
                               + init[(b * NV + cid) * DD + d];
}

// ---------------------------------------------------------------------------
// 7) p-net mean pool (partial sums + atomic combine; g_p_graph pre-zeroed)
// ---------------------------------------------------------------------------
__global__ void p_pool_kernel(const float* __restrict__ node, float* __restrict__ graph) {
    int b = blockIdx.x;
    int r0 = blockIdx.y * 125;             // 4 chunks of 125 rows
    int d = threadIdx.x;
    float s = 0.0f;
    #pragma unroll 5
    for (int i = 0; i < 125; i++)
        s += node[((size_t)(b * NP + r0 + i)) * DD + d];
    atomicAdd(&graph[b * DD + d], s * (1.0f / (float)NP));
}

// ---------------------------------------------------------------------------
// 8) final: out = p_node + p_init + p_graph[b] + v_add[b]
// ---------------------------------------------------------------------------
__global__ void final_kernel(const float* __restrict__ pnode, const float* __restrict__ pinit,
                             const float* __restrict__ pgraph, const float* __restrict__ vadd,
                             float* __restrict__ out) {
    int i4 = blockIdx.x * blockDim.x + threadIdx.x;    // over NPT*64 float4
    if (i4 >= NPT * 64) return;
    int row = i4 >> 6;
    int d4  = i4 & 63;
    int b   = row / NP;
    float4 a = ((const float4*)pnode)[i4];
    float4 c = ((const float4*)pinit)[i4];
    float4 g = ((const float4*)pgraph)[b * 64 + d4];
    float4 v = ((const float4*)vadd)[b * 64 + d4];
    ((float4*)out)[i4] = make_float4(a.x + c.x + g.x + v.x,
                                     a.y + c.y + g.y + v.y,
                                     a.z + c.z + g.z + v.z,
                                     a.w + c.w + g.w + v.w);
}

// ---------------------------------------------------------------------------
// launch
// ---------------------------------------------------------------------------
extern "C" void kernel_launch(void* const* d_in, const int* in_sizes, int n_in,
                              void* d_out, int out_size) {
    const float* v_x      = (const float*)d_in[0];
    const float* p_x      = (const float*)d_in[1];
    const int*   v_src    = (const int*)  d_in[2];
    const int*   v_dst    = (const int*)  d_in[3];
    const int*   p_src    = (const int*)  d_in[4];
    const int*   p_dst    = (const int*)  d_in[5];
    const int*   curr     = (const int*)  d_in[8];
    const float* v_init_W = (const float*)d_in[9];
    const float* v_init_b = (const float*)d_in[10];
    const float* v_W1     = (const float*)d_in[11];
    const float* v_b1     = (const float*)d_in[12];
    const float* v_W2     = (const float*)d_in[13];
    const float* v_b2     = (const float*)d_in[14];
    const float* p_init_W = (const float*)d_in[15];
    const float* p_init_b = (const float*)d_in[16];
    const float* p_W1     = (const float*)d_in[17];
    const float* p_b1     = (const float*)d_in[18];
    const float* p_W2     = (const float*)d_in[19];
    const float* p_b2     = (const float*)d_in[20];
    float* out = (float*)d_out;

    float *pInit, *pA, *pB, *pDinv, *pGraph, *vInit, *vA, *vB, *vDinv, *vAdd;
    int *pCnt, *pList, *vCnt, *vList;
    cudaGetSymbolAddress((void**)&pInit,  g_p_init);
    cudaGetSymbolAddress((void**)&pA,     g_p_bufA);
    cudaGetSymbolAddress((void**)&pB,     g_p_bufB);
    cudaGetSymbolAddress((void**)&pCnt,   g_p_cnt);
    cudaGetSymbolAddress((void**)&pDinv,  g_p_dinv);
    cudaGetSymbolAddress((void**)&pList,  g_p_list);
    cudaGetSymbolAddress((void**)&pGraph, g_p_graph);
    cudaGetSymbolAddress((void**)&vInit,  g_v_init);
    cudaGetSymbolAddress((void**)&vA,     g_v_bufA);
    cudaGetSymbolAddress((void**)&vB,     g_v_bufB);
    cudaGetSymbolAddress((void**)&vCnt,   g_v_cnt);
    cudaGetSymbolAddress((void**)&vDinv,  g_v_dinv);
    cudaGetSymbolAddress((void**)&vList,  g_v_list);
    cudaGetSymbolAddress((void**)&vAdd,   g_v_add);

    // 0) zero counters + p_graph accumulator
    zero_kernel<<<(NPT + 255) / 256, 256>>>();

    // 1) adjacency lists
    build_adj<<<(EP + 255) / 256, 256>>>(p_src, p_dst, pCnt, pList, EP);
    build_adj<<<(EV + 255) / 256, 256>>>(v_src, v_dst, vCnt, vList, EV);

    // 2) dinv
    compute_dinv<<<(NPT + 255) / 256, 256>>>(pCnt, pDinv, NPT);
    compute_dinv<<<(NVT + 255) / 256, 256>>>(vCnt, vDinv, NVT);

    // 3) init embeddings
    init_gemm<FP><<<NPT / 32, 256>>>(p_x, p_init_W, p_init_b, pInit);
    init_gemm<FV><<<NVT / 32, 256>>>(v_x, v_init_W, v_init_b, vInit);

    // 4-5) p-net: two GCN layers
    {
        dim3 g(NPT / 128, 2);
        sgemm_256<<<g, 256>>>(pInit, p_W1, pA);
        agg_kernel<<<NPT / 8, 256>>>(pA, pCnt, pDinv, pList, p_b1, pB, NPT, 1);
        sgemm_256<<<g, 256>>>(pB, p_W2, pA);
        agg_kernel<<<NPT / 8, 256>>>(pA, pCnt, pDinv, pList, p_b2, pB, NPT, 0);
    }
    // v-net: two GCN layers
    {
        dim3 g(NVT / 128, 2);
        sgemm_256<<<g, 256>>>(vInit, v_W1, vA);
        agg_kernel<<<NVT / 8, 256>>>(vA, vCnt, vDinv, vList, v_b1, vB, NVT, 1);
        sgemm_256<<<g, 256>>>(vB, v_W2, vA);
        agg_kernel<<<NVT / 8, 256>>>(vA, vCnt, vDinv, vList, v_b2, vB, NVT, 0);
    }

    // 6) v finalize (graph mean + current-node gather)
    v_final_kernel<<<BB, DD>>>(vB, vInit, curr, vAdd);

    // 7) p graph mean
    {
        dim3 g(BB, 4);
        p_pool_kernel<<<g, DD>>>(pB, pGraph);
    }

    // 8) fuse everything into the output
    final_kernel<<<(NPT * 64 + 255) / 256, 256>>>(pB, pInit, pGraph, vAdd, out);
}

// round 2
// speedup vs baseline: 1.6799x; 1.6799x over previous
#include <cuda_runtime.h>
#include <cuda_bf16.h>
#include <cstdint>

// ---------------------------------------------------------------------------
// Problem constants
// ---------------------------------------------------------------------------
#define BB   128
#define NP   500
#define NV   20
#define DD   256
#define FP   8
#define FV   6
#define NPT  (BB*NP)      // 64000
#define NVT  (BB*NV)      // 2560
#define EP   (NPT*8)
#define EV   (NVT*8)
#define CAP  64
#define KTOT 768          // split-K: [Ah|Ah|Al] x [[Wh],[Wl],[Wh]]
#define SA   40           // smem row stride (bf16) for conflict-free frags

// ---------------------------------------------------------------------------
// Scratch
// ---------------------------------------------------------------------------
__device__ float          g_p_init[NPT * DD];
__device__ float          g_p_H[NPT * DD];
__device__ float          g_p_node[NPT * DD];
__device__ __nv_bfloat16  g_p_Ah[NPT * DD];
__device__ __nv_bfloat16  g_p_Al[NPT * DD];
__device__ int            g_p_cnt[NPT];
__device__ float          g_p_dinv[NPT];
__device__ int            g_p_list[NPT * CAP];
__device__ float          g_p_graph[BB * DD];

__device__ float          g_v_init[NVT * DD];
__device__ float          g_v_H[NVT * DD];
__device__ float          g_v_node[NVT * DD];
__device__ __nv_bfloat16  g_v_Ah[NVT * DD];
__device__ __nv_bfloat16  g_v_Al[NVT * DD];
__device__ int            g_v_cnt[NVT];
__device__ float          g_v_dinv[NVT];
__device__ int            g_v_list[NVT * CAP];
__device__ float          g_v_add[BB * DD];

__device__ __nv_bfloat16  g_Bt_p1[DD * KTOT];
__device__ __nv_bfloat16  g_Bt_p2[DD * KTOT];
__device__ __nv_bfloat16  g_Bt_v1[DD * KTOT];
__device__ __nv_bfloat16  g_Bt_v2[DD * KTOT];

// ---------------------------------------------------------------------------
// helpers
// ---------------------------------------------------------------------------
__device__ __forceinline__ float4 f4_fma(float4 a, float s, float4 acc) {
    acc.x = fmaf(a.x, s, acc.x); acc.y = fmaf(a.y, s, acc.y);
    acc.z = fmaf(a.z, s, acc.z); acc.w = fmaf(a.w, s, acc.w);
    return acc;
}
__device__ __forceinline__ float4 f4_add(float4 a, float4 b) {
    return make_float4(a.x+b.x, a.y+b.y, a.z+b.z, a.w+b.w);
}
__device__ __forceinline__ float4 f4_scale(float4 a, float s) {
    return make_float4(a.x*s, a.y*s, a.z*s, a.w*s);
}
__device__ __forceinline__ float4 f4_relu(float4 a) {
    return make_float4(fmaxf(a.x,0.f), fmaxf(a.y,0.f), fmaxf(a.z,0.f), fmaxf(a.w,0.f));
}
__device__ __forceinline__ uint32_t smem_u32(const void* p) {
    return (uint32_t)__cvta_generic_to_shared(p);
}
__device__ __forceinline__ void cp16(uint32_t dst, const void* src) {
    asm volatile("cp.async.cg.shared.global [%0], [%1], 16;\n" :: "r"(dst), "l"(src));
}
__device__ __forceinline__ void cp_commit() {
    asm volatile("cp.async.commit_group;\n");
}
__device__ __forceinline__ void mma_bf16(float* c, const uint32_t* a, const uint32_t* b) {
    asm volatile(
        "mma.sync.aligned.m16n8k16.row.col.f32.bf16.bf16.f32 "
        "{%0,%1,%2,%3}, {%4,%5,%6,%7}, {%8,%9}, {%0,%1,%2,%3};\n"
        : "+f"(c[0]), "+f"(c[1]), "+f"(c[2]), "+f"(c[3])
        : "r"(a[0]), "r"(a[1]), "r"(a[2]), "r"(a[3]), "r"(b[0]), "r"(b[1]));
}
// write float4 as hi/lo bf16 pairs (4 consecutive elements)
__device__ __forceinline__ void store_f4_split(float4 v, __nv_bfloat16* H,
                                               __nv_bfloat16* L, size_t base) {
    __nv_bfloat16 h0 = __float2bfloat16(v.x), h1 = __float2bfloat16(v.y);
    __nv_bfloat16 h2 = __float2bfloat16(v.z), h3 = __float2bfloat16(v.w);
    __nv_bfloat16 l0 = __float2bfloat16(v.x - __bfloat162float(h0));
    __nv_bfloat16 l1 = __float2bfloat16(v.y - __bfloat162float(h1));
    __nv_bfloat16 l2 = __float2bfloat16(v.z - __bfloat162float(h2));
    __nv_bfloat16 l3 = __float2bfloat16(v.w - __bfloat162float(h3));
    ((__nv_bfloat162*)(H + base))[0] = __nv_bfloat162(h0, h1);
    ((__nv_bfloat162*)(H + base))[1] = __nv_bfloat162(h2, h3);
    ((__nv_bfloat162*)(L + base))[0] = __nv_bfloat162(l0, l1);
    ((__nv_bfloat162*)(L + base))[1] = __nv_bfloat162(l2, l3);
}

// ---------------------------------------------------------------------------
// 0) zero counters / accumulators
// ---------------------------------------------------------------------------
__global__ void zero_kernel() {
    int i = blockIdx.x * blockDim.x + threadIdx.x;
    if (i < NPT)     g_p_cnt[i] = 0;
    if (i < NVT)     g_v_cnt[i] = 0;
    if (i < BB * DD) g_p_graph[i] = 0.0f;
}

// ---------------------------------------------------------------------------
// 1) adjacency (fixed capacity)
// ---------------------------------------------------------------------------
__global__ void build_adj(const int* __restrict__ src, const int* __restrict__ dst,
                          int* __restrict__ cnt, int* __restrict__ list, int E) {
    int e = blockIdx.x * blockDim.x + threadIdx.x;
    if (e >= E) return;
    int d = dst[e];
    int slot = atomicAdd(&cnt[d], 1);
    if (slot < CAP) list[d * CAP + slot] = src[e];
}

// ---------------------------------------------------------------------------
// 2) dinv
// ---------------------------------------------------------------------------
__global__ void compute_dinv(const int* __restrict__ cnt, float* __restrict__ dinv, int N) {
    int i = blockIdx.x * blockDim.x + threadIdx.x;
    if (i < N) dinv[i] = rsqrtf((float)(cnt[i] + 1));
}

// ---------------------------------------------------------------------------
// 3) build transposed split weight:  Bt[n][0:256]=hi(W[k][n]), [256:512]=lo, [512:768]=hi
// ---------------------------------------------------------------------------
__global__ void build_bt(const float* __restrict__ W, __nv_bfloat16* __restrict__ Bt) {
    int n = blockIdx.x;
    int k = threadIdx.x;
    float w = W[k * DD + n];
    __nv_bfloat16 h = __float2bfloat16(w);
    __nv_bfloat16 l = __float2bfloat16(w - __bfloat162float(h));
    Bt[n * KTOT + k]       = h;
    Bt[n * KTOT + 256 + k] = l;
    Bt[n * KTOT + 512 + k] = h;
}

// ---------------------------------------------------------------------------
// 4) init embedding: fp32 + bf16 hi/lo
// ---------------------------------------------------------------------------
template<int F>
__global__ void init_gemm(const float* __restrict__ x, const float* __restrict__ W,
                          const float* __restrict__ b, float* __restrict__ outF,
                          __nv_bfloat16* __restrict__ outH, __nv_bfloat16* __restrict__ outL) {
    __shared__ float Ws[F * DD];
    __shared__ float xs[32 * F];
    __shared__ float bs[DD];
    int t = threadIdx.x;
    for (int i = t; i < F * DD; i += 256) Ws[i] = W[i];
    bs[t] = b[t];
    int row0 = blockIdx.x * 32;
    for (int i = t; i < 32 * F; i += 256) xs[i] = x[row0 * F + i];
    __syncthreads();
    float bias = bs[t];
    #pragma unroll 4
    for (int r = 0; r < 32; r++) {
        float s = bias;
        #pragma unroll
        for (int k = 0; k < F; k++) s = fmaf(xs[r * F + k], Ws[k * DD + t], s);
        size_t idx = (size_t)(row0 + r) * DD + t;
        outF[idx] = s;
        __nv_bfloat16 h = __float2bfloat16(s);
        outH[idx] = h;
        outL[idx] = __float2bfloat16(s - __bfloat162float(h));
    }
}

// ---------------------------------------------------------------------------
// 5) split-bf16 tensor-core GEMM: C[M,256] = sum over K=768 virtual
//    block 128x128, K-chunk 32, double-buffered cp.async, 8 warps (64x32 each)
// ---------------------------------------------------------------------------
__global__ __launch_bounds__(256, 2)
void gemm_split(const __nv_bfloat16* __restrict__ Ah, const __nv_bfloat16* __restrict__ Al,
                const __nv_bfloat16* __restrict__ Bt, float* __restrict__ C) {
    __shared__ __nv_bfloat16 As[2][128 * SA];
    __shared__ __nv_bfloat16 Bs[2][128 * SA];
    const int tid = threadIdx.x;
    const int rowBase = blockIdx.x * 128;
    const int colBase = blockIdx.y * 128;
    const int lr  = tid >> 2;          // 0..63
    const int lk8 = (tid & 3) * 8;     // 0,8,16,24
    const int wid = tid >> 5, lane = tid & 31;
    const int wm = wid & 1, wn = wid >> 1;   // 2 x 4 warps
    const int g = lane >> 2, q = lane & 3;

    float acc[4][4][4];
    #pragma unroll
    for (int mi = 0; mi < 4; mi++)
        #pragma unroll
        for (int ni = 0; ni < 4; ni++)
            #pragma unroll
            for (int r = 0; r < 4; r++) acc[mi][ni][r] = 0.0f;

    auto issue = [&](int buf, int kc) {
        const __nv_bfloat16* Asrc = (kc >= 16) ? Al : Ah;
        int kcol = (kc & 7) * 32;
        const __nv_bfloat16* aPtr = Asrc + (size_t)(rowBase + lr) * 256 + kcol + lk8;
        const __nv_bfloat16* bPtr = Bt + (size_t)(colBase + lr) * KTOT + kc * 32 + lk8;
        cp16(smem_u32(&As[buf][lr * SA + lk8]), aPtr);
        cp16(smem_u32(&As[buf][(lr + 64) * SA + lk8]), aPtr + (size_t)64 * 256);
        cp16(smem_u32(&Bs[buf][lr * SA + lk8]), bPtr);
        cp16(smem_u32(&Bs[buf][(lr + 64) * SA + lk8]), bPtr + (size_t)64 * KTOT);
        cp_commit();
    };

    issue(0, 0);
    for (int kc = 0; kc < 24; kc++) {
        int cur = kc & 1;
        if (kc < 23) {
            issue(cur ^ 1, kc + 1);
            asm volatile("cp.async.wait_group 1;\n");
        } else {
            asm volatile("cp.async.wait_group 0;\n");
        }
        __syncthreads();
        const __nv_bfloat16* as = As[cur];
        const __nv_bfloat16* bs = Bs[cur];
        #pragma unroll
        for (int ks = 0; ks < 32; ks += 16) {
            uint32_t afr[4][4], bfr[4][2];
            #pragma unroll
            for (int mi = 0; mi < 4; mi++) {
                int r = wm * 64 + mi * 16 + g;
                afr[mi][0] = *(const uint32_t*)&as[r * SA + ks + q * 2];
                afr[mi][1] = *(const uint32_t*)&as[(r + 8) * SA + ks + q * 2];
                afr[mi][2] = *(const uint32_t*)&as[r * SA + ks + 8 + q * 2];
                afr[mi][3] = *(const uint32_t*)&as[(r + 8) * SA + ks + 8 + q * 2];
            }
            #pragma unroll
            for (int ni = 0; ni < 4; ni++) {
                int n = wn * 32 + ni * 8 + g;
                bfr[ni][0] = *(const uint32_t*)&bs[n * SA + ks + q * 2];
                bfr[ni][1] = *(const uint32_t*)&bs[n * SA + ks + 8 + q * 2];
            }
            #pragma unroll
            for (int mi = 0; mi < 4; mi++)
                #pragma unroll
                for (int ni = 0; ni < 4; ni++)
                    mma_bf16(acc[mi][ni], afr[mi], bfr[ni]);
        }
        __syncthreads();
    }

    #pragma unroll
    for (int mi = 0; mi < 4; mi++) {
        int r = rowBase + wm * 64 + mi * 16 + g;
        #pragma unroll
        for (int ni = 0; ni < 4; ni++) {
            int c = colBase + wn * 32 + ni * 8 + q * 2;
            *(float2*)&C[(size_t)r * 256 + c] = make_float2(acc[mi][ni][0], acc[mi][ni][1]);
            *(float2*)&C[(size_t)(r + 8) * 256 + c] = make_float2(acc[mi][ni][2], acc[mi][ni][3]);
        }
    }
}

// ---------------------------------------------------------------------------
// 6) GCN aggregation (gather), one warp per node; emits fp32 and/or bf16 hi/lo
// ---------------------------------------------------------------------------
__global__ void agg_kernel(const float* __restrict__ h, const int* __restrict__ cnt,
                           const float* __restrict__ dinv, const int* __restrict__ list,
                           const float* __restrict__ bias,
                           float* __restrict__ outF,
                           __nv_bfloat16* __restrict__ outH, __nv_bfloat16* __restrict__ outL,
                           int N, int doRelu) {
    int w = (blockIdx.x * blockDim.x + threadIdx.x) >> 5;
    int lane = threadIdx.x & 31;
    if (w >= N) return;
    int rawc = cnt[w];
    int c = rawc < CAP ? rawc : CAP;
    float dd = dinv[w];
    float selfw = 1.0f / (float)(rawc + 1);

    const float4* h4 = (const float4*)h;
    float4 acc0 = f4_scale(h4[(size_t)w * 64 + lane], selfw);
    float4 acc1 = f4_scale(h4[(size_t)w * 64 + 32 + lane], selfw);

    const int* mylist = &list[w * CAP];
    for (int j = 0; j < c; j++) {
        int s = mylist[j];
        float cf = dinv[s] * dd;
        acc0 = f4_fma(h4[(size_t)s * 64 + lane], cf, acc0);
        acc1 = f4_fma(h4[(size_t)s * 64 + 32 + lane], cf, acc1);
    }
    const float4* b4 = (const float4*)bias;
    acc0 = f4_add(acc0, b4[lane]);
    acc1 = f4_add(acc1, b4[32 + lane]);
    if (doRelu) { acc0 = f4_relu(acc0); acc1 = f4_relu(acc1); }
    if (outF) {
        float4* o4 = (float4*)outF;
        o4[(size_t)w * 64 + lane]      = acc0;
        o4[(size_t)w * 64 + 32 + lane] = acc1;
    }
    if (outH) {
        size_t base0 = (size_t)w * 256 + lane * 4;
        store_f4_split(acc0, outH, outL, base0);
        store_f4_split(acc1, outH, outL, base0 + 128);
    }
}

// ---------------------------------------------------------------------------
// 7) v finalize
// ---------------------------------------------------------------------------
__global__ void v_final_kernel(const float* __restrict__ node, const float* __restrict__ init,
                               const int* __restrict__ curr, float* __restrict__ vadd) {
    int b = blockIdx.x;
    int d = threadIdx.x;
    float s = 0.0f;
    #pragma unroll
    for (int i = 0; i < NV; i++) s += node[(b * NV + i) * DD + d];
    float gmean = s * (1.0f / (float)NV);
    int cid = curr[b];
    vadd[b * DD + d] = 2.0f * gmean + node[(b * NV + cid) * DD + d]
                                    + init[(b * NV + cid) * DD + d];
}

// ---------------------------------------------------------------------------
// 8) p graph mean pool
// ---------------------------------------------------------------------------
__global__ void p_pool_kernel(const float* __restrict__ node, float* __restrict__ graph) {
    int b = blockIdx.x;
    int r0 = blockIdx.y * 125;
    int d = threadIdx.x;
    float s = 0.0f;
    #pragma unroll 5
    for (int i = 0; i < 125; i++)
        s += node[((size_t)(b * NP + r0 + i)) * DD + d];
    atomicAdd(&graph[b * DD + d], s * (1.0f / (float)NP));
}

// ---------------------------------------------------------------------------
// 9) final fuse
// ---------------------------------------------------------------------------
__global__ void final_kernel(const float* __restrict__ pnode, const float* __restrict__ pinit,
                             const float* __restrict__ pgraph, const float* __restrict__ vadd,
                             float* __restrict__ out) {
    int i4 = blockIdx.x * blockDim.x + threadIdx.x;
    if (i4 >= NPT * 64) return;
    int row = i4 >> 6;
    int d4  = i4 & 63;
    int b   = row / NP;
    float4 a = ((const float4*)pnode)[i4];
    float4 c = ((const float4*)pinit)[i4];
    float4 g = ((const float4*)pgraph)[b * 64 + d4];
    float4 v = ((const float4*)vadd)[b * 64 + d4];
    ((float4*)out)[i4] = make_float4(a.x + c.x + g.x + v.x,
                                     a.y + c.y + g.y + v.y,
                                     a.z + c.z + g.z + v.z,
                                     a.w + c.w + g.w + v.w);
}

// ---------------------------------------------------------------------------
// launch
// ---------------------------------------------------------------------------
extern "C" void kernel_launch(void* const* d_in, const int* in_sizes, int n_in,
                              void* d_out, int out_size) {
    const float* v_x      = (const float*)d_in[0];
    const float* p_x      = (const float*)d_in[1];
    const int*   v_src    = (const int*)  d_in[2];
    const int*   v_dst    = (const int*)  d_in[3];
    const int*   p_src    = (const int*)  d_in[4];
    const int*   p_dst    = (const int*)  d_in[5];
    const int*   curr     = (const int*)  d_in[8];
    const float* v_init_W = (const float*)d_in[9];
    const float* v_init_b = (const float*)d_in[10];
    const float* v_W1     = (const float*)d_in[11];
    const float* v_b1     = (const float*)d_in[12];
    const float* v_W2     = (const float*)d_in[13];
    const float* v_b2     = (const float*)d_in[14];
    const float* p_init_W = (const float*)d_in[15];
    const float* p_init_b = (const float*)d_in[16];
    const float* p_W1     = (const float*)d_in[17];
    const float* p_b1     = (const float*)d_in[18];
    const float* p_W2     = (const float*)d_in[19];
    const float* p_b2     = (const float*)d_in[20];
    float* out = (float*)d_out;

    float *pInit, *pH, *pNode, *pDinv, *pGraph;
    float *vInit, *vH, *vNode, *vDinv, *vAdd;
    __nv_bfloat16 *pAh, *pAl, *vAh, *vAl, *btP1, *btP2, *btV1, *btV2;
    int *pCnt, *pList, *vCnt, *vList;
    cudaGetSymbolAddress((void**)&pInit,  g_p_init);
    cudaGetSymbolAddress((void**)&pH,     g_p_H);
    cudaGetSymbolAddress((void**)&pNode,  g_p_node);
    cudaGetSymbolAddress((void**)&pAh,    g_p_Ah);
    cudaGetSymbolAddress((void**)&pAl,    g_p_Al);
    cudaGetSymbolAddress((void**)&pCnt,   g_p_cnt);
    cudaGetSymbolAddress((void**)&pDinv,  g_p_dinv);
    cudaGetSymbolAddress((void**)&pList,  g_p_list);
    cudaGetSymbolAddress((void**)&pGraph, g_p_graph);
    cudaGetSymbolAddress((void**)&vInit,  g_v_init);
    cudaGetSymbolAddress((void**)&vH,     g_v_H);
    cudaGetSymbolAddress((void**)&vNode,  g_v_node);
    cudaGetSymbolAddress((void**)&vAh,    g_v_Ah);
    cudaGetSymbolAddress((void**)&vAl,    g_v_Al);
    cudaGetSymbolAddress((void**)&vCnt,   g_v_cnt);
    cudaGetSymbolAddress((void**)&vDinv,  g_v_dinv);
    cudaGetSymbolAddress((void**)&vList,  g_v_list);
    cudaGetSymbolAddress((void**)&vAdd,   g_v_add);
    cudaGetSymbolAddress((void**)&btP1,   g_Bt_p1);
    cudaGetSymbolAddress((void**)&btP2,   g_Bt_p2);
    cudaGetSymbolAddress((void**)&btV1,   g_Bt_v1);
    cudaGetSymbolAddress((void**)&btV2,   g_Bt_v2);

    // launch order arranged so the profiler's skip-5 capture lands on the big p-GEMM
    zero_kernel<<<(NPT + 255) / 256, 256>>>();                                // 1
    build_adj<<<(EP + 255) / 256, 256>>>(p_src, p_dst, pCnt, pList, EP);      // 2
    build_bt<<<DD, DD>>>(p_W1, btP1);                                         // 3
    init_gemm<FP><<<NPT / 32, 256>>>(p_x, p_init_W, p_init_b,
                                     pInit, pAh, pAl);                        // 4
    {
        dim3 gp(NPT / 128, 2);
        gemm_split<<<gp, 256>>>(pAh, pAl, btP1, pH);                          // 5 (captured)
        compute_dinv<<<(NPT + 255) / 256, 256>>>(pCnt, pDinv, NPT);           // 6
        agg_kernel<<<NPT / 8, 256>>>(pH, pCnt, pDinv, pList, p_b1,
                                     nullptr, pAh, pAl, NPT, 1);              // 7
        build_bt<<<DD, DD>>>(p_W2, btP2);                                     // 8
        gemm_split<<<gp, 256>>>(pAh, pAl, btP2, pH);                          // 9
        agg_kernel<<<NPT / 8, 256>>>(pH, pCnt, pDinv, pList, p_b2,
                                     pNode, nullptr, nullptr, NPT, 0);        // 10
    }
    // v-net
    build_adj<<<(EV + 255) / 256, 256>>>(v_src, v_dst, vCnt, vList, EV);
    compute_dinv<<<(NVT + 255) / 256, 256>>>(vCnt, vDinv, NVT);
    build_bt<<<DD, DD>>>(v_W1, btV1);
    build_bt<<<DD, DD>>>(v_W2, btV2);
    init_gemm<FV><<<NVT / 32, 256>>>(v_x, v_init_W, v_init_b, vInit, vAh, vAl);
    {
        dim3 gv(NVT / 128, 2);
        gemm_split<<<gv, 256>>>(vAh, vAl, btV1, vH);
        agg_kernel<<<NVT / 8, 256>>>(vH, vCnt, vDinv, vList, v_b1,
                                     nullptr, vAh, vAl, NVT, 1);
        gemm_split<<<gv, 256>>>(vAh, vAl, btV2, vH);
        agg_kernel<<<NVT / 8, 256>>>(vH, vCnt, vDinv, vList, v_b2,
                                     vNode, nullptr, nullptr, NVT, 0);
    }

    v_final_kernel<<<BB, DD>>>(vNode, vInit, curr, vAdd);
    {
        dim3 g(BB, 4);
        p_pool_kernel<<<g, DD>>>(pNode, pGraph);
    }
    final_kernel<<<(NPT * 64 + 255) / 256, 256>>>(pNode, pInit, pGraph, vAdd, out);
}

// round 5
// speedup vs baseline: 1.8226x; 1.0850x over previous
#include <cuda_runtime.h>
#include <cuda_bf16.h>
#include <cstdint>

// ---------------------------------------------------------------------------
// Problem constants
// ---------------------------------------------------------------------------
#define BB   128
#define NP   500
#define NV   20
#define DD   256
#define FP   8
#define FV   6
#define NPT  (BB*NP)      // 64000
#define NVT  (BB*NV)      // 2560
#define NT   (NPT+NVT)    // 66560 combined rows (p first, then v)
#define EP   (NPT*8)
#define EV   (NVT*8)
#define ET   (EP+EV)
#define CAP  64
#define KTOT 768          // split-K: [Ah|Ah|Al] x [[Wh],[Wl],[Wh]]
#define SA   40           // smem row stride (bf16), conflict-free for ldmatrix

// ---------------------------------------------------------------------------
// Scratch (combined p+v buffers; v rows live at offset NPT)
// ---------------------------------------------------------------------------
__device__ float          g_init[NT * DD];
__device__ float          g_H[NT * DD];
__device__ float          g_node[NT * DD];
__device__ __align__(128) __nv_bfloat16 g_Ah[NT * DD];
__device__ __align__(128) __nv_bfloat16 g_Al[NT * DD];
__device__ int            g_cnt[NT];
__device__ float          g_dinv[NT];
__device__ int            g_list[NT * CAP];
__device__ float          g_p_graph[BB * DD];
__device__ float          g_v_add[BB * DD];

__device__ __align__(128) __nv_bfloat16 g_Bt_p1[DD * KTOT];
__device__ __align__(128) __nv_bfloat16 g_Bt_p2[DD * KTOT];
__device__ __align__(128) __nv_bfloat16 g_Bt_v1[DD * KTOT];
__device__ __align__(128) __nv_bfloat16 g_Bt_v2[DD * KTOT];

// ---------------------------------------------------------------------------
// helpers
// ---------------------------------------------------------------------------
__device__ __forceinline__ uint32_t smem_u32(const void* p) {
    return (uint32_t)__cvta_generic_to_shared(p);
}
__device__ __forceinline__ void cp16(uint32_t dst, const void* src) {
    asm volatile("cp.async.cg.shared.global [%0], [%1], 16;\n" :: "r"(dst), "l"(src));
}
__device__ __forceinline__ void cp_commit() {
    asm volatile("cp.async.commit_group;\n");
}
__device__ __forceinline__ void ldsm_x4(uint32_t* r, uint32_t addr) {
    asm volatile("ldmatrix.sync.aligned.m8n8.x4.shared.b16 {%0,%1,%2,%3}, [%4];"
                 : "=r"(r[0]), "=r"(r[1]), "=r"(r[2]), "=r"(r[3]) : "r"(addr));
}
__device__ __forceinline__ void mma_bf16(float* c, const uint32_t* a,
                                         uint32_t b0, uint32_t b1) {
    asm volatile(
        "mma.sync.aligned.m16n8k16.row.col.f32.bf16.bf16.f32 "
        "{%0,%1,%2,%3}, {%4,%5,%6,%7}, {%8,%9}, {%0,%1,%2,%3};\n"
        : "+f"(c[0]), "+f"(c[1]), "+f"(c[2]), "+f"(c[3])
        : "r"(a[0]), "r"(a[1]), "r"(a[2]), "r"(a[3]), "r"(b0), "r"(b1));
}
__device__ __forceinline__ float4 f4_fma(float4 a, float s, float4 acc) {
    acc.x = fmaf(a.x, s, acc.x); acc.y = fmaf(a.y, s, acc.y);
    acc.z = fmaf(a.z, s, acc.z); acc.w = fmaf(a.w, s, acc.w);
    return acc;
}
__device__ __forceinline__ float4 f4_add(float4 a, float4 b) {
    return make_float4(a.x+b.x, a.y+b.y, a.z+b.z, a.w+b.w);
}
__device__ __forceinline__ float4 f4_scale(float4 a, float s) {
    return make_float4(a.x*s, a.y*s, a.z*s, a.w*s);
}
__device__ __forceinline__ float4 f4_relu(float4 a) {
    return make_float4(fmaxf(a.x,0.f), fmaxf(a.y,0.f), fmaxf(a.z,0.f), fmaxf(a.w,0.f));
}
__device__ __forceinline__ void store_f4_split(float4 v, __nv_bfloat16* H,
                                               __nv_bfloat16* L, size_t base) {
    __nv_bfloat16 h0 = __float2bfloat16(v.x), h1 = __float2bfloat16(v.y);
    __nv_bfloat16 h2 = __float2bfloat16(v.z), h3 = __float2bfloat16(v.w);
    __nv_bfloat16 l0 = __float2bfloat16(v.x - __bfloat162float(h0));
    __nv_bfloat16 l1 = __float2bfloat16(v.y - __bfloat162float(h1));
    __nv_bfloat16 l2 = __float2bfloat16(v.z - __bfloat162float(h2));
    __nv_bfloat16 l3 = __float2bfloat16(v.w - __bfloat162float(h3));
    ((__nv_bfloat162*)(H + base))[0] = __nv_bfloat162(h0, h1);
    ((__nv_bfloat162*)(H + base))[1] = __nv_bfloat162(h2, h3);
    ((__nv_bfloat162*)(L + base))[0] = __nv_bfloat162(l0, l1);
    ((__nv_bfloat162*)(L + base))[1] = __nv_bfloat162(l2, l3);
}

// ---------------------------------------------------------------------------
// 1) zero counters / accumulators   (grid 260 x 256)
// ---------------------------------------------------------------------------
__global__ void zero_kernel() {
    int i = blockIdx.x * blockDim.x + threadIdx.x;
    if (i < NT)      g_cnt[i] = 0;
    if (i < BB * DD) g_p_graph[i] = 0.0f;
}

// ---------------------------------------------------------------------------
// 2) combined adjacency (p edges then v edges; v node ids offset by NPT)
// ---------------------------------------------------------------------------
__global__ void build_adj(const int* __restrict__ p_src, const int* __restrict__ p_dst,
                          const int* __restrict__ v_src, const int* __restrict__ v_dst) {
    int e = blockIdx.x * blockDim.x + threadIdx.x;
    if (e >= ET) return;
    int s, d;
    if (e < EP) { s = p_src[e];        d = p_dst[e]; }
    else        { s = v_src[e-EP]+NPT; d = v_dst[e-EP]+NPT; }
    int slot = atomicAdd(&g_cnt[d], 1);
    if (slot < CAP) g_list[d * CAP + slot] = s;
}

// ---------------------------------------------------------------------------
// 3) prep: init embeddings (p+v) + weight splits (4) + dinv, one kernel
//    blocks [0,2080): init; [2080,2336): bt; [2336,...): dinv
// ---------------------------------------------------------------------------
__global__ void prep2(const float* __restrict__ p_x, const float* __restrict__ v_x,
                      const float* __restrict__ pIW, const float* __restrict__ pIb,
                      const float* __restrict__ vIW, const float* __restrict__ vIb,
                      const float* __restrict__ pW1, const float* __restrict__ pW2,
                      const float* __restrict__ vW1, const float* __restrict__ vW2) {
    int bx = blockIdx.x;
    int t = threadIdx.x;
    if (bx < 2080) {
        const bool isP = bx < 2000;
        const float* x  = isP ? p_x : v_x;
        const float* W  = isP ? pIW : vIW;
        const float* bi = isP ? pIb : vIb;
        const int F = isP ? FP : FV;
        const int localRow0 = isP ? bx * 32 : (bx - 2000) * 32;
        const int outRow0   = isP ? localRow0 : NPT + localRow0;
        __shared__ float Ws[FP * DD];
        __shared__ float xs[32 * FP];
        __shared__ float bs[DD];
        for (int i = t; i < F * DD; i += 256) Ws[i] = W[i];
        bs[t] = bi[t];
        for (int i = t; i < 32 * F; i += 256) xs[i] = x[(size_t)localRow0 * F + i];
        __syncthreads();
        float bias = bs[t];
        for (int r = 0; r < 32; r++) {
            float s = bias;
            for (int k = 0; k < F; k++) s = fmaf(xs[r * F + k], Ws[k * DD + t], s);
            size_t idx = (size_t)(outRow0 + r) * DD + t;
            g_init[idx] = s;
            __nv_bfloat16 h = __float2bfloat16(s);
            g_Ah[idx] = h;
            g_Al[idx] = __float2bfloat16(s - __bfloat162float(h));
        }
    } else if (bx < 2336) {
        int n = bx - 2080;
        int k = t;
        const float* Wsrc[4] = {pW1, pW2, vW1, vW2};
        __nv_bfloat16* Bts[4];
        Bts[0] = g_Bt_p1; Bts[1] = g_Bt_p2; Bts[2] = g_Bt_v1; Bts[3] = g_Bt_v2;
        #pragma unroll
        for (int j = 0; j < 4; j++) {
            float w = Wsrc[j][k * DD + n];
            __nv_bfloat16 h = __float2bfloat16(w);
            __nv_bfloat16 l = __float2bfloat16(w - __bfloat162float(h));
            __nv_bfloat16* Bt = Bts[j];
            Bt[n * KTOT + k]       = h;
            Bt[n * KTOT + 256 + k] = l;
            Bt[n * KTOT + 512 + k] = h;
        }
    } else {
        int i = (bx - 2336) * 256 + t;
        if (i < NT) g_dinv[i] = rsqrtf((float)(g_cnt[i] + 1));
    }
}

// ---------------------------------------------------------------------------
// 4) split-bf16 tensor-core GEMM with ldmatrix fragment loads.
//    C[row,256] = [Ah|Ah|Al] @ BtT ; blocks <500 use p weights, >=500 v.
//    128x128 CTA tile, 8 warps of 64x32, K-chunk 32, double-buffered cp.async.
// ---------------------------------------------------------------------------
__global__ __launch_bounds__(256, 2)
void tc_gemm(const __nv_bfloat16* __restrict__ Ah, const __nv_bfloat16* __restrict__ Al,
             const __nv_bfloat16* __restrict__ BtP, const __nv_bfloat16* __restrict__ BtV,
             float* __restrict__ C) {
    __shared__ __nv_bfloat16 As[2][128 * SA];
    __shared__ __nv_bfloat16 Bs[2][128 * SA];
    const __nv_bfloat16* Bt = (blockIdx.x < 500) ? BtP : BtV;
    const int tid = threadIdx.x;
    const int rowBase = blockIdx.x * 128;
    const int colBase = blockIdx.y * 128;
    const int lr  = tid >> 2;          // 0..63
    const int lk8 = (tid & 3) * 8;     // 0,8,16,24
    const int wid = tid >> 5, lane = tid & 31;
    const int wm = wid & 1, wn = wid >> 1;   // warps: 2 (m) x 4 (n)
    const int g = lane >> 2, q = lane & 3;

    float acc[4][4][4];
    #pragma unroll
    for (int mi = 0; mi < 4; mi++)
        #pragma unroll
        for (int ni = 0; ni < 4; ni++)
            #pragma unroll
            for (int r = 0; r < 4; r++) acc[mi][ni][r] = 0.0f;

    auto issue = [&](int buf, int kc) {
        const __nv_bfloat16* Asrc = (kc >= 16) ? Al : Ah;
        int kcol = (kc & 7) * 32;
        const __nv_bfloat16* aPtr = Asrc + (size_t)(rowBase + lr) * 256 + kcol + lk8;
        const __nv_bfloat16* bPtr = Bt + (size_t)(colBase + lr) * KTOT + kc * 32 + lk8;
        cp16(smem_u32(&As[buf][lr * SA + lk8]), aPtr);
        cp16(smem_u32(&As[buf][(lr + 64) * SA + lk8]), aPtr + (size_t)64 * 256);
        cp16(smem_u32(&Bs[buf][lr * SA + lk8]), bPtr);
        cp16(smem_u32(&Bs[buf][(lr + 64) * SA + lk8]), bPtr + (size_t)64 * KTOT);
        cp_commit();
    };

    // ldmatrix per-lane address components
    const int aRowOff = (lane & 15);          // row within 16-row tile
    const int aKHalf  = (lane >> 4) * 8;      // 0 or 8
    const int bRowOff = (lane & 7) + ((lane >> 4) << 3);  // 0..15 (n within pair)
    const int bKHalf  = ((lane >> 3) & 1) * 8;

    issue(0, 0);
    for (int kc = 0; kc < 24; kc++) {
        int cur = kc & 1;
        if (kc < 23) {
            issue(cur ^ 1, kc + 1);
            asm volatile("cp.async.wait_group 1;\n" ::: "memory");
        } else {
            asm volatile("cp.async.wait_group 0;\n" ::: "memory");
        }
        __syncthreads();
        const __nv_bfloat16* as = As[cur];
        const __nv_bfloat16* bs = Bs[cur];
        #pragma unroll
        for (int ks = 0; ks < 32; ks += 16) {
            uint32_t afr[4][4], bfr[2][4];
            #pragma unroll
            for (int mi = 0; mi < 4; mi++) {
                int r = wm * 64 + mi * 16 + aRowOff;
                ldsm_x4(afr[mi], smem_u32(&as[r * SA + ks + aKHalf]));
            }
            #pragma unroll
            for (int pr = 0; pr < 2; pr++) {
                int n = wn * 32 + pr * 16 + bRowOff;
                ldsm_x4(bfr[pr], smem_u32(&bs[n * SA + ks + bKHalf]));
            }
            #pragma unroll
            for (int mi = 0; mi < 4; mi++)
                #pragma unroll
                for (int ni = 0; ni < 4; ni++)
                    mma_bf16(acc[mi][ni], afr[mi],
                             bfr[ni >> 1][(ni & 1) * 2], bfr[ni >> 1][(ni & 1) * 2 + 1]);
        }
        __syncthreads();
    }

    #pragma unroll
    for (int mi = 0; mi < 4; mi++) {
        int r = rowBase + wm * 64 + mi * 16 + g;
        #pragma unroll
        for (int ni = 0; ni < 4; ni++) {
            int c = colBase + wn * 32 + ni * 8 + q * 2;
            *(float2*)&C[(size_t)r * 256 + c] = make_float2(acc[mi][ni][0], acc[mi][ni][1]);
            *(float2*)&C[(size_t)(r + 8) * 256 + c] = make_float2(acc[mi][ni][2], acc[mi][ni][3]);
        }
    }
}

// ---------------------------------------------------------------------------
// 5) combined GCN aggregation (gather), one warp per node
// ---------------------------------------------------------------------------
__global__ void agg_kernel(const float* __restrict__ h,
                           const float* __restrict__ bias_p,
                           const float* __restrict__ bias_v,
                           float* __restrict__ outF,
                           __nv_bfloat16* __restrict__ outH, __nv_bfloat16* __restrict__ outL,
                           int doRelu) {
    int w = (blockIdx.x * blockDim.x + threadIdx.x) >> 5;
    int lane = threadIdx.x & 31;
    if (w >= NT) return;
    int rawc = g_cnt[w];
    int c = rawc < CAP ? rawc : CAP;
    float dd = g_dinv[w];
    float selfw = 1.0f / (float)(rawc + 1);

    const float4* h4 = (const float4*)h;
    float4 acc0 = f4_scale(h4[(size_t)w * 64 + lane], selfw);
    float4 acc1 = f4_scale(h4[(size_t)w * 64 + 32 + lane], selfw);

    const int* mylist = &g_list[w * CAP];
    for (int j = 0; j < c; j++) {
        int s = mylist[j];
        float cf = g_dinv[s] * dd;
        acc0 = f4_fma(h4[(size_t)s * 64 + lane], cf, acc0);
        acc1 = f4_fma(h4[(size_t)s * 64 + 32 + lane], cf, acc1);
    }
    const float4* b4 = (const float4*)(w < NPT ? bias_p : bias_v);
    acc0 = f4_add(acc0, b4[lane]);
    acc1 = f4_add(acc1, b4[32 + lane]);
    if (doRelu) { acc0 = f4_relu(acc0); acc1 = f4_relu(acc1); }
    if (outF) {
        float4* o4 = (float4*)outF;
        o4[(size_t)w * 64 + lane]      = acc0;
        o4[(size_t)w * 64 + 32 + lane] = acc1;
    }
    if (outH) {
        size_t base0 = (size_t)w * 256 + lane * 4;
        store_f4_split(acc0, outH, outL, base0);
        store_f4_split(acc1, outH, outL, base0 + 128);
    }
}

// ---------------------------------------------------------------------------
// 6) pool + v-finalize, one kernel: blocks [0,128) v_final, [128,640) p_pool
// ---------------------------------------------------------------------------
__global__ void pool_vfinal(const int* __restrict__ curr) {
    int bx = blockIdx.x;
    int d = threadIdx.x;
    if (bx < BB) {
        int b = bx;
        const float* node = g_node + (size_t)NPT * DD;
        const float* init = g_init + (size_t)NPT * DD;
        float s = 0.0f;
        #pragma unroll
        for (int i = 0; i < NV; i++) s += node[(b * NV + i) * DD + d];
        float gmean = s * (1.0f / (float)NV);
        int cid = curr[b];
        g_v_add[b * DD + d] = 2.0f * gmean + node[(b * NV + cid) * DD + d]
                                           + init[(b * NV + cid) * DD + d];
    } else {
        int z = bx - BB;
        int b = z & 127;
        int r0 = (z >> 7) * 125;
        float s = 0.0f;
        #pragma unroll 5
        for (int i = 0; i < 125; i++)
            s += g_node[((size_t)(b * NP + r0 + i)) * DD + d];
        atomicAdd(&g_p_graph[b * DD + d], s * (1.0f / (float)NP));
    }
}

// ---------------------------------------------------------------------------
// 7) final fuse
// ---------------------------------------------------------------------------
__global__ void final_kernel(float* __restrict__ out) {
    int i4 = blockIdx.x * blockDim.x + threadIdx.x;
    if (i4 >= NPT * 64) return;
    int row = i4 >> 6;
    int d4  = i4 & 63;
    int b   = row / NP;
    float4 a = ((const float4*)g_node)[i4];
    float4 c = ((const float4*)g_init)[i4];
    float4 g = ((const float4*)g_p_graph)[b * 64 + d4];
    float4 v = ((const float4*)g_v_add)[b * 64 + d4];
    ((float4*)out)[i4] = make_float4(a.x + c.x + g.x + v.x,
                                     a.y + c.y + g.y + v.y,
                                     a.z + c.z + g.z + v.z,
                                     a.w + c.w + g.w + v.w);
}

// ---------------------------------------------------------------------------
// launch
// ---------------------------------------------------------------------------
extern "C" void kernel_launch(void* const* d_in, const int* in_sizes, int n_in,
                              void* d_out, int out_size) {
    const float* v_x      = (const float*)d_in[0];
    const float* p_x      = (const float*)d_in[1];
    const int*   v_src    = (const int*)  d_in[2];
    const int*   v_dst    = (const int*)  d_in[3];
    const int*   p_src    = (const int*)  d_in[4];
    const int*   p_dst    = (const int*)  d_in[5];
    const int*   curr     = (const int*)  d_in[8];
    const float* v_init_W = (const float*)d_in[9];
    const float* v_init_b = (const float*)d_in[10];
    const float* v_W1     = (const float*)d_in[11];
    const float* v_b1     = (const float*)d_in[12];
    const float* v_W2     = (const float*)d_in[13];
    const float* v_b2     = (const float*)d_in[14];
    const float* p_init_W = (const float*)d_in[15];
    const float* p_init_b = (const float*)d_in[16];
    const float* p_W1     = (const float*)d_in[17];
    const float* p_b1     = (const float*)d_in[18];
    const float* p_W2     = (const float*)d_in[19];
    const float* p_b2     = (const float*)d_in[20];
    float* out = (float*)d_out;

    float *H, *node, *initB;
    __nv_bfloat16 *Ah, *Al, *btP1, *btP2, *btV1, *btV2;
    cudaGetSymbolAddress((void**)&H,     g_H);
    cudaGetSymbolAddress((void**)&node,  g_node);
    cudaGetSymbolAddress((void**)&initB, g_init);
    cudaGetSymbolAddress((void**)&Ah,    g_Ah);
    cudaGetSymbolAddress((void**)&Al,    g_Al);
    cudaGetSymbolAddress((void**)&btP1,  g_Bt_p1);
    cudaGetSymbolAddress((void**)&btP2,  g_Bt_p2);
    cudaGetSymbolAddress((void**)&btV1,  g_Bt_v1);
    cudaGetSymbolAddress((void**)&btV2,  g_Bt_v2);

    dim3 gemmGrid(NT / 128, 2);   // 520 x 2

    // 1) zero
    zero_kernel<<<(NT + 255) / 256, 256>>>();
    // 2) combined adjacency
    build_adj<<<(ET + 255) / 256, 256>>>(p_src, p_dst, v_src, v_dst);
    // 3) prep: init-embed + bt + dinv
    prep2<<<2080 + 256 + (NT + 255) / 256, 256>>>(p_x, v_x, p_init_W, p_init_b,
                                                  v_init_W, v_init_b,
                                                  p_W1, p_W2, v_W1, v_W2);
    // 4) layer-1 GEMM (captured by ncu)
    tc_gemm<<<gemmGrid, 256>>>(Ah, Al, btP1, btV1, H);
    // 5) layer-1 agg (+relu) -> bf16 split
    agg_kernel<<<NT / 8, 256>>>(H, p_b1, v_b1, nullptr, Ah, Al, 1);
    // 6) layer-2 GEMM
    tc_gemm<<<gemmGrid, 256>>>(Ah, Al, btP2, btV2, H);
    // 7) layer-2 agg -> fp32 node
    agg_kernel<<<NT / 8, 256>>>(H, p_b2, v_b2, node, nullptr, nullptr, 0);
    // 8) pool + v finalize
    pool_vfinal<<<BB + BB * 4, DD>>>(curr);
    // 9) final fuse
    final_kernel<<<(NPT * 64 + 255) / 256, 256>>>(out);
}